// round 13
// baseline (speedup 1.0000x reference)
#include <cuda_runtime.h>
#include <math.h>
#include <stdint.h>

// Problem constants
#define D_MODEL 1024
#define NH      16
#define DK_     64
#define MROWS   4096      // B*L = 2*2048
#define DFF_    4096
#define SEQL    2048

// ---------------------------------------------------------------------------
// Scratch (static device globals; no allocations allowed)
// ---------------------------------------------------------------------------
__device__ float g_q   [MROWS * D_MODEL];
__device__ float g_k   [MROWS * D_MODEL];
__device__ float g_v   [MROWS * D_MODEL];
__device__ float g_ctx [MROWS * D_MODEL];
__device__ float g_proj[MROWS * D_MODEL];
__device__ float g_x1  [MROWS * D_MODEL];
__device__ float g_x2  [MROWS * D_MODEL];
__device__ float g_ff  [MROWS * DFF_];

__device__ __forceinline__ float gelu_exact(float x) {
    return 0.5f * x * (1.0f + erff(x * 0.70710678118654752f));
}

__device__ __forceinline__ uint32_t to_tf32_bits(float x) {
    uint32_t u;
    asm volatile("cvt.rna.tf32.f32 %0, %1;" : "=r"(u) : "f"(x));
    return u;
}

__device__ __forceinline__ void mma_tf32(float* c, const uint32_t* a, const uint32_t* b) {
    asm volatile(
        "mma.sync.aligned.m16n8k8.row.col.f32.tf32.tf32.f32 "
        "{%0,%1,%2,%3}, {%4,%5,%6,%7}, {%8,%9}, {%0,%1,%2,%3};\n"
        : "+f"(c[0]), "+f"(c[1]), "+f"(c[2]), "+f"(c[3])
        : "r"(a[0]), "r"(a[1]), "r"(a[2]), "r"(a[3]), "r"(b[0]), "r"(b[1]));
}

// cp.async helpers
__device__ __forceinline__ void cp_async16(void* smem, const void* gmem) {
    uint32_t s = (uint32_t)__cvta_generic_to_shared(smem);
    asm volatile("cp.async.cg.shared.global [%0], [%1], 16;\n" :: "r"(s), "l"(gmem));
}
__device__ __forceinline__ void cp_commit() {
    asm volatile("cp.async.commit_group;\n" ::: "memory");
}
template<int N>
__device__ __forceinline__ void cp_wait() {
    asm volatile("cp.async.wait_group %0;\n" :: "n"(N) : "memory");
}

// ---------------------------------------------------------------------------
// TF32 tensor-core GEMM, cp.async 3-stage pipeline, GBK=8 — R4 EXACT
// (best measured). C = A@B + bias, ACT 0=none 1=gelu.
// ---------------------------------------------------------------------------
#define GBM 128
#define GBN 128
#define GBK 8
#define APAD 20
#define BPAD 136
#define STAGES 3

template<int ACT>
__global__ __launch_bounds__(256, 2)
void gemm_tf32(const float* __restrict__ A, const float* __restrict__ B,
               const float* __restrict__ bias, float* __restrict__ C,
               int M, int N, int K)
{
    __shared__ float As[STAGES][GBM][APAD];
    __shared__ float Bs[STAGES][GBK][BPAD];

    const int t    = threadIdx.x;
    const int wid  = t >> 5;
    const int lane = t & 31;
    const int wm   = wid >> 2;
    const int wn   = wid & 3;
    const int lr   = lane >> 2;
    const int lc   = lane & 3;

    const int m0 = blockIdx.y * GBM;
    const int n0 = blockIdx.x * GBN;

    const int arow = t >> 1;
    const int acol = (t & 1) * 4;
    const int brow = t >> 5;
    const int bcol = (t & 31) * 4;

    const float* Ag = A + (size_t)(m0 + arow) * K + acol;
    const float* Bg = B + (size_t)brow * N + n0 + bcol;

    float acc[4][4][4];
#pragma unroll
    for (int i = 0; i < 4; i++)
#pragma unroll
        for (int j = 0; j < 4; j++)
#pragma unroll
            for (int r = 0; r < 4; r++) acc[i][j][r] = 0.0f;

    const int kTiles = K / GBK;

#pragma unroll
    for (int s = 0; s < 2; s++) {
        cp_async16(&As[s][arow][acol], Ag + (size_t)s * GBK);
        cp_async16(&Bs[s][brow][bcol], Bg + (size_t)s * GBK * N);
        cp_commit();
    }

    int p = 0;
    for (int kt = 0; kt < kTiles; kt++) {
        cp_wait<1>();
        __syncthreads();

        uint32_t afr[4][4];
        uint32_t bfr[4][2];
#pragma unroll
        for (int mf = 0; mf < 4; mf++) {
            const int m = wm * 64 + mf * 16 + lr;
            afr[mf][0] = __float_as_uint(As[p][m    ][lc]);
            afr[mf][1] = __float_as_uint(As[p][m + 8][lc]);
            afr[mf][2] = __float_as_uint(As[p][m    ][lc + 4]);
            afr[mf][3] = __float_as_uint(As[p][m + 8][lc + 4]);
        }
#pragma unroll
        for (int nf = 0; nf < 4; nf++) {
            const int n = wn * 32 + nf * 8 + lr;
            bfr[nf][0] = __float_as_uint(Bs[p][lc    ][n]);
            bfr[nf][1] = __float_as_uint(Bs[p][lc + 4][n]);
        }
#pragma unroll
        for (int mf = 0; mf < 4; mf++)
#pragma unroll
            for (int nf = 0; nf < 4; nf++)
                mma_tf32(acc[mf][nf], afr[mf], bfr[nf]);

        if (kt + 2 < kTiles) {
            const int s = (p + 2) % STAGES;
            const size_t ko = (size_t)(kt + 2) * GBK;
            cp_async16(&As[s][arow][acol], Ag + ko);
            cp_async16(&Bs[s][brow][bcol], Bg + ko * N);
        }
        cp_commit();

        p = (p + 1) % STAGES;
        __syncthreads();
    }

#pragma unroll
    for (int mf = 0; mf < 4; mf++) {
        const int r0 = m0 + wm * 64 + mf * 16 + lr;
#pragma unroll
        for (int nf = 0; nf < 4; nf++) {
            const int c0 = n0 + wn * 32 + nf * 8 + 2 * lc;
            const float b0 = bias[c0], b1 = bias[c0 + 1];
            float v0 = acc[mf][nf][0] + b0;
            float v1 = acc[mf][nf][1] + b1;
            float v2 = acc[mf][nf][2] + b0;
            float v3 = acc[mf][nf][3] + b1;
            if (ACT == 1) {
                v0 = gelu_exact(v0); v1 = gelu_exact(v1);
                v2 = gelu_exact(v2); v3 = gelu_exact(v3);
            }
            *(float2*)(C + (size_t)r0 * N + c0)       = make_float2(v0, v1);
            *(float2*)(C + (size_t)(r0 + 8) * N + c0) = make_float2(v2, v3);
        }
    }
}

// ---------------------------------------------------------------------------
// Tensor-core flash attention (TF32 mma), DK=64.
// cp.async double-buffered K/V (R12, measured win) + NEW: warp M-tile 32 rows
// (two m16 accumulator groups share every K/V B-fragment -> LDS/mma halved).
// CTA covers 256 Q rows, 8 warps.
// ---------------------------------------------------------------------------
#define KS_STRIDE 68
#define VS_STRIDE 72
#define KS_ELEMS (64 * KS_STRIDE)
#define VS_ELEMS (64 * VS_STRIDE)
#define ATTN_SMEM ((2 * KS_ELEMS + 2 * VS_ELEMS) * 4)   // 71680 B

template<bool CAUSAL>
__global__ __launch_bounds__(256)
void flash_attn_tc(const float* __restrict__ Q, const float* __restrict__ K,
                   const float* __restrict__ V, float* __restrict__ O, int L)
{
    extern __shared__ float asmem[];
    float* KsB = asmem;
    float* VsB = asmem + 2 * KS_ELEMS;

    const int t    = threadIdx.x;
    const int lane = t & 31;
    const int w    = t >> 5;
    const int lr   = lane >> 2;
    const int lc   = lane & 3;

    const int qt = blockIdx.x;
    const int bh = blockIdx.y;
    const int b  = bh >> 4;
    const int h  = bh & 15;
    const int q0 = qt * 256;
    const int wrow = q0 + w * 32;          // warp's first Q row (32 rows/warp)

    const float* Qb = Q + (size_t)(b * L) * D_MODEL + h * DK_;
    const float* Kb = K + (size_t)(b * L) * D_MODEL + h * DK_;
    const float* Vb = V + (size_t)(b * L) * D_MODEL + h * DK_;

    // load-tile mapping: 1024 16B-chunks per matrix, 4/thread
    int ldrow[4], ldc4[4];
#pragma unroll
    for (int i = 0; i < 4; i++) {
        const int idx = i * 256 + t;
        ldrow[i] = idx >> 4;
        ldc4[i]  = (idx & 15) * 4;
    }

    // Q fragments for two m16 groups (scale 1/8 folded in)
    uint32_t qf[2][8][4];
#pragma unroll
    for (int g = 0; g < 2; g++) {
        const float* qr0 = Qb + (size_t)(wrow + g * 16 + lr) * D_MODEL;
        const float* qr1 = Qb + (size_t)(wrow + g * 16 + lr + 8) * D_MODEL;
#pragma unroll
        for (int kc = 0; kc < 8; kc++) {
            qf[g][kc][0] = to_tf32_bits(0.125f * qr0[8 * kc + lc]);
            qf[g][kc][1] = to_tf32_bits(0.125f * qr1[8 * kc + lc]);
            qf[g][kc][2] = to_tf32_bits(0.125f * qr0[8 * kc + lc + 4]);
            qf[g][kc][3] = to_tf32_bits(0.125f * qr1[8 * kc + lc + 4]);
        }
    }

    float o[2][8][4];
#pragma unroll
    for (int g = 0; g < 2; g++)
#pragma unroll
        for (int nf = 0; nf < 8; nf++)
#pragma unroll
            for (int i = 0; i < 4; i++) o[g][nf][i] = 0.0f;
    float mrow[4] = {-1e30f, -1e30f, -1e30f, -1e30f};
    float lrow[4] = {0.f, 0.f, 0.f, 0.f};

    const int ntile = CAUSAL ? (4 * qt + 4) : (L >> 6);

    // Prologue: async-load tile 0 into buffer 0
#pragma unroll
    for (int i = 0; i < 4; i++) {
        const size_t g = (size_t)ldrow[i] * D_MODEL + ldc4[i];
        cp_async16(&KsB[0 * KS_ELEMS + ldrow[i] * KS_STRIDE + ldc4[i]], Kb + g);
        cp_async16(&VsB[0 * VS_ELEMS + ldrow[i] * VS_STRIDE + ldc4[i]], Vb + g);
    }
    cp_commit();

    int p = 0;
    for (int kt = 0; kt < ntile; kt++) {
        cp_wait<0>();
        __syncthreads();

        if (kt + 1 < ntile) {
            const int k0n = (kt + 1) * 64;
            const int q2 = p ^ 1;
#pragma unroll
            for (int i = 0; i < 4; i++) {
                const size_t g = (size_t)(k0n + ldrow[i]) * D_MODEL + ldc4[i];
                cp_async16(&KsB[q2 * KS_ELEMS + ldrow[i] * KS_STRIDE + ldc4[i]], Kb + g);
                cp_async16(&VsB[q2 * VS_ELEMS + ldrow[i] * VS_STRIDE + ldc4[i]], Vb + g);
            }
        }
        cp_commit();

        const int k0 = kt * 64;
        const bool active = (!CAUSAL) || (k0 <= wrow + 31);
        if (active) {
            const float* Ks = KsB + p * KS_ELEMS;
            const float* Vs = VsB + p * VS_ELEMS;

            // ---- S = Q K^T : B-fragment shared by both m-groups ----
            float sacc[2][8][4];
#pragma unroll
            for (int nf = 0; nf < 8; nf++) {
                sacc[0][nf][0] = sacc[0][nf][1] = sacc[0][nf][2] = sacc[0][nf][3] = 0.0f;
                sacc[1][nf][0] = sacc[1][nf][1] = sacc[1][nf][2] = sacc[1][nf][3] = 0.0f;
#pragma unroll
                for (int kc = 0; kc < 8; kc++) {
                    uint32_t bfr[2];
                    bfr[0] = __float_as_uint(Ks[(8 * nf + lr) * KS_STRIDE + 8 * kc + lc]);
                    bfr[1] = __float_as_uint(Ks[(8 * nf + lr) * KS_STRIDE + 8 * kc + lc + 4]);
                    mma_tf32(sacc[0][nf], qf[0][kc], bfr);
                    mma_tf32(sacc[1][nf], qf[1][kc], bfr);
                }
            }

            // ---- causal mask on near-diagonal tiles ----
            if (CAUSAL && (k0 + 63 > wrow)) {
#pragma unroll
                for (int g = 0; g < 2; g++) {
                    const int rA = wrow + g * 16 + lr;
                    const int rB = rA + 8;
#pragma unroll
                    for (int nf = 0; nf < 8; nf++) {
                        const int key = k0 + 8 * nf + 2 * lc;
                        if (key     > rA) sacc[g][nf][0] = -1e30f;
                        if (key + 1 > rA) sacc[g][nf][1] = -1e30f;
                        if (key     > rB) sacc[g][nf][2] = -1e30f;
                        if (key + 1 > rB) sacc[g][nf][3] = -1e30f;
                    }
                }
            }

            // ---- online softmax (4 row-sets) ----
            float mx[4] = {-1e30f, -1e30f, -1e30f, -1e30f};
#pragma unroll
            for (int g = 0; g < 2; g++)
#pragma unroll
                for (int nf = 0; nf < 8; nf++) {
                    mx[2*g]   = fmaxf(mx[2*g],   fmaxf(sacc[g][nf][0], sacc[g][nf][1]));
                    mx[2*g+1] = fmaxf(mx[2*g+1], fmaxf(sacc[g][nf][2], sacc[g][nf][3]));
                }
#pragma unroll
            for (int i = 0; i < 4; i++) {
                mx[i] = fmaxf(mx[i], __shfl_xor_sync(0xffffffffu, mx[i], 1));
                mx[i] = fmaxf(mx[i], __shfl_xor_sync(0xffffffffu, mx[i], 2));
            }
            float nm[4], cr[4], sum[4];
#pragma unroll
            for (int i = 0; i < 4; i++) {
                nm[i] = fmaxf(mrow[i], mx[i]);
                cr[i] = __expf(mrow[i] - nm[i]);
                sum[i] = 0.f;
            }
#pragma unroll
            for (int g = 0; g < 2; g++)
#pragma unroll
                for (int nf = 0; nf < 8; nf++) {
                    sacc[g][nf][0] = __expf(sacc[g][nf][0] - nm[2*g]);
                    sacc[g][nf][1] = __expf(sacc[g][nf][1] - nm[2*g]);
                    sacc[g][nf][2] = __expf(sacc[g][nf][2] - nm[2*g+1]);
                    sacc[g][nf][3] = __expf(sacc[g][nf][3] - nm[2*g+1]);
                    sum[2*g]   += sacc[g][nf][0] + sacc[g][nf][1];
                    sum[2*g+1] += sacc[g][nf][2] + sacc[g][nf][3];
                }
#pragma unroll
            for (int i = 0; i < 4; i++) {
                sum[i] += __shfl_xor_sync(0xffffffffu, sum[i], 1);
                sum[i] += __shfl_xor_sync(0xffffffffu, sum[i], 2);
                lrow[i] = lrow[i] * cr[i] + sum[i];
                mrow[i] = nm[i];
            }
#pragma unroll
            for (int g = 0; g < 2; g++)
#pragma unroll
                for (int nf = 0; nf < 8; nf++) {
                    o[g][nf][0] *= cr[2*g];   o[g][nf][1] *= cr[2*g];
                    o[g][nf][2] *= cr[2*g+1]; o[g][nf][3] *= cr[2*g+1];
                }

            // ---- O += P V : V B-fragment shared by both m-groups ----
            const int qbase = lane & ~3;
            const int srcA  = qbase | (lc >> 1);
            const int srcB  = srcA + 2;
#pragma unroll
            for (int kc = 0; kc < 8; kc++) {
                uint32_t af[2][4];
#pragma unroll
                for (int g = 0; g < 2; g++) {
                    const float p0a = __shfl_sync(0xffffffffu, sacc[g][kc][0], srcA);
                    const float p1a = __shfl_sync(0xffffffffu, sacc[g][kc][1], srcA);
                    const float p2a = __shfl_sync(0xffffffffu, sacc[g][kc][2], srcA);
                    const float p3a = __shfl_sync(0xffffffffu, sacc[g][kc][3], srcA);
                    const float p0b = __shfl_sync(0xffffffffu, sacc[g][kc][0], srcB);
                    const float p1b = __shfl_sync(0xffffffffu, sacc[g][kc][1], srcB);
                    const float p2b = __shfl_sync(0xffffffffu, sacc[g][kc][2], srcB);
                    const float p3b = __shfl_sync(0xffffffffu, sacc[g][kc][3], srcB);
                    const bool odd = (lc & 1);
                    af[g][0] = __float_as_uint(odd ? p1a : p0a);
                    af[g][1] = __float_as_uint(odd ? p3a : p2a);
                    af[g][2] = __float_as_uint(odd ? p1b : p0b);
                    af[g][3] = __float_as_uint(odd ? p3b : p2b);
                }
#pragma unroll
                for (int nf = 0; nf < 8; nf++) {
                    uint32_t bfr[2];
                    bfr[0] = __float_as_uint(Vs[(8 * kc + lc)     * VS_STRIDE + 8 * nf + lr]);
                    bfr[1] = __float_as_uint(Vs[(8 * kc + lc + 4) * VS_STRIDE + 8 * nf + lr]);
                    mma_tf32(o[0][nf], af[0], bfr);
                    mma_tf32(o[1][nf], af[1], bfr);
                }
            }
        }
        p ^= 1;
    }

    // epilogue: 4 row-sets
#pragma unroll
    for (int g = 0; g < 2; g++) {
        const float invA = 1.0f / lrow[2*g];
        const float invB = 1.0f / lrow[2*g+1];
        float* OA = O + (size_t)(b * L + wrow + g * 16 + lr) * D_MODEL + h * DK_;
        float* OB = O + (size_t)(b * L + wrow + g * 16 + lr + 8) * D_MODEL + h * DK_;
#pragma unroll
        for (int nf = 0; nf < 8; nf++) {
            const int c = 8 * nf + 2 * lc;
            *(float2*)(OA + c) = make_float2(o[g][nf][0] * invA, o[g][nf][1] * invA);
            *(float2*)(OB + c) = make_float2(o[g][nf][2] * invB, o[g][nf][3] * invB);
        }
    }
}

// ---------------------------------------------------------------------------
// Fused residual add + LayerNorm over last dim (1024). 1 block / row.
// ---------------------------------------------------------------------------
__global__ __launch_bounds__(128)
void add_layernorm(const float* __restrict__ A, const float* __restrict__ Bb,
                   const float* __restrict__ g, const float* __restrict__ be,
                   float* __restrict__ out)
{
    const int row = blockIdx.x;
    const int t = threadIdx.x;
    const float* a = A  + (size_t)row * D_MODEL;
    const float* b = Bb + (size_t)row * D_MODEL;

    float v[8];
    float s = 0.f, sq = 0.f;
#pragma unroll
    for (int i = 0; i < 8; i++) {
        const int c = t + i * 128;
        v[i] = a[c] + b[c];
        s += v[i];
        sq = fmaf(v[i], v[i], sq);
    }
#pragma unroll
    for (int o = 16; o > 0; o >>= 1) {
        s  += __shfl_down_sync(0xffffffffu, s,  o);
        sq += __shfl_down_sync(0xffffffffu, sq, o);
    }
    __shared__ float rs[4], rq[4];
    __shared__ float mean_s, rstd_s;
    const int w = t >> 5, ln = t & 31;
    if (ln == 0) { rs[w] = s; rq[w] = sq; }
    __syncthreads();
    if (t == 0) {
        const float S  = rs[0] + rs[1] + rs[2] + rs[3];
        const float Q2 = rq[0] + rq[1] + rq[2] + rq[3];
        const float mean = S * (1.0f / 1024.0f);
        const float var  = Q2 * (1.0f / 1024.0f) - mean * mean;
        mean_s = mean;
        rstd_s = rsqrtf(var + 1e-5f);
    }
    __syncthreads();
    const float mean = mean_s, rstd = rstd_s;
    float* op = out + (size_t)row * D_MODEL;
#pragma unroll
    for (int i = 0; i < 8; i++) {
        const int c = t + i * 128;
        op[c] = (v[i] - mean) * rstd * g[c] + be[c];
    }
}

// ---------------------------------------------------------------------------
// Host launcher
// ---------------------------------------------------------------------------
static float* devptr(const void* sym) {
    void* p = nullptr;
    cudaGetSymbolAddress(&p, sym);
    return (float*)p;
}

extern "C" void kernel_launch(void* const* d_in, const int* in_sizes, int n_in,
                              void* d_out, int out_size)
{
    const float* x   = (const float*)d_in[0];
    const float* enc = (const float*)d_in[1];
    const float* swq = (const float*)d_in[4];
    const float* sbq = (const float*)d_in[5];
    const float* swk = (const float*)d_in[6];
    const float* sbk = (const float*)d_in[7];
    const float* swv = (const float*)d_in[8];
    const float* sbv = (const float*)d_in[9];
    const float* swo = (const float*)d_in[10];
    const float* sbo = (const float*)d_in[11];
    const float* cwq = (const float*)d_in[12];
    const float* cbq = (const float*)d_in[13];
    const float* cwk = (const float*)d_in[14];
    const float* cbk = (const float*)d_in[15];
    const float* cwv = (const float*)d_in[16];
    const float* cbv = (const float*)d_in[17];
    const float* cwo = (const float*)d_in[18];
    const float* cbo = (const float*)d_in[19];
    const float* fw1 = (const float*)d_in[20];
    const float* fb1 = (const float*)d_in[21];
    const float* fw2 = (const float*)d_in[22];
    const float* fb2 = (const float*)d_in[23];
    const float* n1g = (const float*)d_in[24];
    const float* n1b = (const float*)d_in[25];
    const float* n2g = (const float*)d_in[26];
    const float* n2b = (const float*)d_in[27];
    const float* n3g = (const float*)d_in[28];
    const float* n3b = (const float*)d_in[29];
    float* out = (float*)d_out;

    float* q    = devptr(g_q);
    float* k    = devptr(g_k);
    float* v    = devptr(g_v);
    float* ctx  = devptr(g_ctx);
    float* proj = devptr(g_proj);
    float* x1   = devptr(g_x1);
    float* x2   = devptr(g_x2);
    float* ff   = devptr(g_ff);

    static bool attr_done = false;
    if (!attr_done) {
        cudaFuncSetAttribute(flash_attn_tc<true>,  cudaFuncAttributeMaxDynamicSharedMemorySize, ATTN_SMEM);
        cudaFuncSetAttribute(flash_attn_tc<false>, cudaFuncAttributeMaxDynamicSharedMemorySize, ATTN_SMEM);
        attr_done = true;
    }

    const int M = MROWS, Dm = D_MODEL, Dff = DFF_;
    dim3 blk(256);
    dim3 gP (Dm  / GBN, M / GBM);   // (8, 32)
    dim3 gF1(Dff / GBN, M / GBM);   // (32, 32)
    dim3 gA (SEQL / 256, 32);       // (8, B*H)

    // ---- self attention ----
    gemm_tf32<0><<<gP, blk>>>(x, swq, sbq, q, M, Dm, Dm);
    gemm_tf32<0><<<gP, blk>>>(x, swk, sbk, k, M, Dm, Dm);
    gemm_tf32<0><<<gP, blk>>>(x, swv, sbv, v, M, Dm, Dm);
    flash_attn_tc<true><<<gA, 256, ATTN_SMEM>>>(q, k, v, ctx, SEQL);
    gemm_tf32<0><<<gP, blk>>>(ctx, swo, sbo, proj, M, Dm, Dm);
    add_layernorm<<<M, 128>>>(x, proj, n1g, n1b, x1);

    // ---- cross attention ----
    gemm_tf32<0><<<gP, blk>>>(x1,  cwq, cbq, q, M, Dm, Dm);
    gemm_tf32<0><<<gP, blk>>>(enc, cwk, cbk, k, M, Dm, Dm);
    gemm_tf32<0><<<gP, blk>>>(enc, cwv, cbv, v, M, Dm, Dm);
    flash_attn_tc<false><<<gA, 256, ATTN_SMEM>>>(q, k, v, ctx, SEQL);
    gemm_tf32<0><<<gP, blk>>>(ctx, cwo, cbo, proj, M, Dm, Dm);
    add_layernorm<<<M, 128>>>(x1, proj, n2g, n2b, x2);

    // ---- feed-forward ----
    gemm_tf32<1><<<gF1, blk>>>(x2, fw1, fb1, ff, M, Dff, Dm);
    gemm_tf32<0><<<gP,  blk>>>(ff, fw2, fb2, proj, M, Dm, Dff);
    add_layernorm<<<M, 128>>>(x2, proj, n3g, n3b, out);
}

// round 14
// speedup vs baseline: 1.4893x; 1.4893x over previous
#include <cuda_runtime.h>
#include <math.h>
#include <stdint.h>

// Problem constants
#define D_MODEL 1024
#define NH      16
#define DK_     64
#define MROWS   4096      // B*L = 2*2048
#define DFF_    4096
#define SEQL    2048

// ---------------------------------------------------------------------------
// Scratch (static device globals; no allocations allowed)
// ---------------------------------------------------------------------------
__device__ float g_q   [MROWS * D_MODEL];
__device__ float g_k   [MROWS * D_MODEL];
__device__ float g_v   [MROWS * D_MODEL];
__device__ float g_ctx [MROWS * D_MODEL];
__device__ float g_proj[MROWS * D_MODEL];
__device__ float g_x1  [MROWS * D_MODEL];
__device__ float g_x2  [MROWS * D_MODEL];
__device__ float g_ff  [MROWS * DFF_];

__device__ __forceinline__ float gelu_exact(float x) {
    return 0.5f * x * (1.0f + erff(x * 0.70710678118654752f));
}

__device__ __forceinline__ uint32_t to_tf32_bits(float x) {
    uint32_t u;
    asm volatile("cvt.rna.tf32.f32 %0, %1;" : "=r"(u) : "f"(x));
    return u;
}

__device__ __forceinline__ void mma_tf32(float* c, const uint32_t* a, const uint32_t* b) {
    asm volatile(
        "mma.sync.aligned.m16n8k8.row.col.f32.tf32.tf32.f32 "
        "{%0,%1,%2,%3}, {%4,%5,%6,%7}, {%8,%9}, {%0,%1,%2,%3};\n"
        : "+f"(c[0]), "+f"(c[1]), "+f"(c[2]), "+f"(c[3])
        : "r"(a[0]), "r"(a[1]), "r"(a[2]), "r"(a[3]), "r"(b[0]), "r"(b[1]));
}

// cp.async helpers
__device__ __forceinline__ void cp_async16(void* smem, const void* gmem) {
    uint32_t s = (uint32_t)__cvta_generic_to_shared(smem);
    asm volatile("cp.async.cg.shared.global [%0], [%1], 16;\n" :: "r"(s), "l"(gmem));
}
__device__ __forceinline__ void cp_commit() {
    asm volatile("cp.async.commit_group;\n" ::: "memory");
}
template<int N>
__device__ __forceinline__ void cp_wait() {
    asm volatile("cp.async.wait_group %0;\n" :: "n"(N) : "memory");
}

// ---------------------------------------------------------------------------
// TF32 tensor-core GEMM, cp.async 3-stage pipeline, GBK=8 — R4-exact inner
// loop. BATCHED over blockIdx.z: up to 3 independent (B, bias, C) triples
// sharing the same A. Merges the QKV / cross-KV projections into one launch
// to eliminate wave quantization.
// ---------------------------------------------------------------------------
#define GBM 128
#define GBN 128
#define GBK 8
#define APAD 20
#define BPAD 136
#define STAGES 3

struct GemmBatch {
    const float* B[3];
    const float* bias[3];
    float*       C[3];
};

template<int ACT>
__global__ __launch_bounds__(256, 2)
void gemm_tf32(const float* __restrict__ A, GemmBatch gb,
               int M, int N, int K)
{
    __shared__ float As[STAGES][GBM][APAD];
    __shared__ float Bs[STAGES][GBK][BPAD];

    const float* __restrict__ B    = gb.B[blockIdx.z];
    const float* __restrict__ bias = gb.bias[blockIdx.z];
    float* __restrict__       C    = gb.C[blockIdx.z];

    const int t    = threadIdx.x;
    const int wid  = t >> 5;
    const int lane = t & 31;
    const int wm   = wid >> 2;
    const int wn   = wid & 3;
    const int lr   = lane >> 2;
    const int lc   = lane & 3;

    const int m0 = blockIdx.y * GBM;
    const int n0 = blockIdx.x * GBN;

    const int arow = t >> 1;
    const int acol = (t & 1) * 4;
    const int brow = t >> 5;
    const int bcol = (t & 31) * 4;

    const float* Ag = A + (size_t)(m0 + arow) * K + acol;
    const float* Bg = B + (size_t)brow * N + n0 + bcol;

    float acc[4][4][4];
#pragma unroll
    for (int i = 0; i < 4; i++)
#pragma unroll
        for (int j = 0; j < 4; j++)
#pragma unroll
            for (int r = 0; r < 4; r++) acc[i][j][r] = 0.0f;

    const int kTiles = K / GBK;

#pragma unroll
    for (int s = 0; s < 2; s++) {
        cp_async16(&As[s][arow][acol], Ag + (size_t)s * GBK);
        cp_async16(&Bs[s][brow][bcol], Bg + (size_t)s * GBK * N);
        cp_commit();
    }

    int p = 0;
    for (int kt = 0; kt < kTiles; kt++) {
        cp_wait<1>();
        __syncthreads();

        uint32_t afr[4][4];
        uint32_t bfr[4][2];
#pragma unroll
        for (int mf = 0; mf < 4; mf++) {
            const int m = wm * 64 + mf * 16 + lr;
            afr[mf][0] = __float_as_uint(As[p][m    ][lc]);
            afr[mf][1] = __float_as_uint(As[p][m + 8][lc]);
            afr[mf][2] = __float_as_uint(As[p][m    ][lc + 4]);
            afr[mf][3] = __float_as_uint(As[p][m + 8][lc + 4]);
        }
#pragma unroll
        for (int nf = 0; nf < 4; nf++) {
            const int n = wn * 32 + nf * 8 + lr;
            bfr[nf][0] = __float_as_uint(Bs[p][lc    ][n]);
            bfr[nf][1] = __float_as_uint(Bs[p][lc + 4][n]);
        }
#pragma unroll
        for (int mf = 0; mf < 4; mf++)
#pragma unroll
            for (int nf = 0; nf < 4; nf++)
                mma_tf32(acc[mf][nf], afr[mf], bfr[nf]);

        if (kt + 2 < kTiles) {
            const int s = (p + 2) % STAGES;
            const size_t ko = (size_t)(kt + 2) * GBK;
            cp_async16(&As[s][arow][acol], Ag + ko);
            cp_async16(&Bs[s][brow][bcol], Bg + ko * N);
        }
        cp_commit();

        p = (p + 1) % STAGES;
        __syncthreads();
    }

#pragma unroll
    for (int mf = 0; mf < 4; mf++) {
        const int r0 = m0 + wm * 64 + mf * 16 + lr;
#pragma unroll
        for (int nf = 0; nf < 4; nf++) {
            const int c0 = n0 + wn * 32 + nf * 8 + 2 * lc;
            const float b0 = bias[c0], b1 = bias[c0 + 1];
            float v0 = acc[mf][nf][0] + b0;
            float v1 = acc[mf][nf][1] + b1;
            float v2 = acc[mf][nf][2] + b0;
            float v3 = acc[mf][nf][3] + b1;
            if (ACT == 1) {
                v0 = gelu_exact(v0); v1 = gelu_exact(v1);
                v2 = gelu_exact(v2); v3 = gelu_exact(v3);
            }
            *(float2*)(C + (size_t)r0 * N + c0)       = make_float2(v0, v1);
            *(float2*)(C + (size_t)(r0 + 8) * N + c0) = make_float2(v2, v3);
        }
    }
}

// ---------------------------------------------------------------------------
// Tensor-core flash attention (TF32 mma), DK=64 — R12 EXACT (measured best:
// cp.async double-buffered K/V, 128-row Q tiles, 16 rows/warp).
// ---------------------------------------------------------------------------
#define KS_STRIDE 68
#define VS_STRIDE 72
#define KS_ELEMS (64 * KS_STRIDE)
#define VS_ELEMS (64 * VS_STRIDE)
#define ATTN_SMEM ((2 * KS_ELEMS + 2 * VS_ELEMS) * 4)   // 71680 B

template<bool CAUSAL>
__global__ __launch_bounds__(256)
void flash_attn_tc(const float* __restrict__ Q, const float* __restrict__ K,
                   const float* __restrict__ V, float* __restrict__ O, int L)
{
    extern __shared__ float asmem[];
    float* KsB = asmem;
    float* VsB = asmem + 2 * KS_ELEMS;

    const int t    = threadIdx.x;
    const int lane = t & 31;
    const int w    = t >> 5;
    const int lr   = lane >> 2;
    const int lc   = lane & 3;

    const int qt = blockIdx.x;
    const int bh = blockIdx.y;
    const int b  = bh >> 4;
    const int h  = bh & 15;
    const int q0 = qt * 128;
    const int wrow = q0 + w * 16;

    const float* Qb = Q + (size_t)(b * L) * D_MODEL + h * DK_;
    const float* Kb = K + (size_t)(b * L) * D_MODEL + h * DK_;
    const float* Vb = V + (size_t)(b * L) * D_MODEL + h * DK_;

    int ldrow[4], ldc4[4];
#pragma unroll
    for (int i = 0; i < 4; i++) {
        const int idx = i * 256 + t;
        ldrow[i] = idx >> 4;
        ldc4[i]  = (idx & 15) * 4;
    }

    uint32_t qf[8][4];
    {
        const float* qr0 = Qb + (size_t)(wrow + lr) * D_MODEL;
        const float* qr1 = Qb + (size_t)(wrow + lr + 8) * D_MODEL;
#pragma unroll
        for (int kc = 0; kc < 8; kc++) {
            qf[kc][0] = to_tf32_bits(0.125f * qr0[8 * kc + lc]);
            qf[kc][1] = to_tf32_bits(0.125f * qr1[8 * kc + lc]);
            qf[kc][2] = to_tf32_bits(0.125f * qr0[8 * kc + lc + 4]);
            qf[kc][3] = to_tf32_bits(0.125f * qr1[8 * kc + lc + 4]);
        }
    }

    float o[8][4];
#pragma unroll
    for (int nf = 0; nf < 8; nf++)
#pragma unroll
        for (int i = 0; i < 4; i++) o[nf][i] = 0.0f;
    float m0r = -1e30f, m1r = -1e30f;
    float l0r = 0.0f,  l1r = 0.0f;

    const int ntile = CAUSAL ? (2 * qt + 2) : (L >> 6);

#pragma unroll
    for (int i = 0; i < 4; i++) {
        const size_t g = (size_t)ldrow[i] * D_MODEL + ldc4[i];
        cp_async16(&KsB[0 * KS_ELEMS + ldrow[i] * KS_STRIDE + ldc4[i]], Kb + g);
        cp_async16(&VsB[0 * VS_ELEMS + ldrow[i] * VS_STRIDE + ldc4[i]], Vb + g);
    }
    cp_commit();

    int p = 0;
    for (int kt = 0; kt < ntile; kt++) {
        cp_wait<0>();
        __syncthreads();

        if (kt + 1 < ntile) {
            const int k0n = (kt + 1) * 64;
            const int q2 = p ^ 1;
#pragma unroll
            for (int i = 0; i < 4; i++) {
                const size_t g = (size_t)(k0n + ldrow[i]) * D_MODEL + ldc4[i];
                cp_async16(&KsB[q2 * KS_ELEMS + ldrow[i] * KS_STRIDE + ldc4[i]], Kb + g);
                cp_async16(&VsB[q2 * VS_ELEMS + ldrow[i] * VS_STRIDE + ldc4[i]], Vb + g);
            }
        }
        cp_commit();

        const int k0 = kt * 64;
        const bool active = (!CAUSAL) || (k0 <= wrow + 15);
        if (active) {
            const float* Ks = KsB + p * KS_ELEMS;
            const float* Vs = VsB + p * VS_ELEMS;

            float sacc[8][4];
#pragma unroll
            for (int nf = 0; nf < 8; nf++) {
                sacc[nf][0] = sacc[nf][1] = sacc[nf][2] = sacc[nf][3] = 0.0f;
#pragma unroll
                for (int kc = 0; kc < 8; kc++) {
                    uint32_t bfr[2];
                    bfr[0] = __float_as_uint(Ks[(8 * nf + lr) * KS_STRIDE + 8 * kc + lc]);
                    bfr[1] = __float_as_uint(Ks[(8 * nf + lr) * KS_STRIDE + 8 * kc + lc + 4]);
                    mma_tf32(sacc[nf], qf[kc], bfr);
                }
            }

            if (CAUSAL && (k0 + 63 > wrow)) {
                const int r0 = wrow + lr, r1 = wrow + lr + 8;
#pragma unroll
                for (int nf = 0; nf < 8; nf++) {
                    const int key = k0 + 8 * nf + 2 * lc;
                    if (key     > r0) sacc[nf][0] = -1e30f;
                    if (key + 1 > r0) sacc[nf][1] = -1e30f;
                    if (key     > r1) sacc[nf][2] = -1e30f;
                    if (key + 1 > r1) sacc[nf][3] = -1e30f;
                }
            }

            float mx0 = -1e30f, mx1 = -1e30f;
#pragma unroll
            for (int nf = 0; nf < 8; nf++) {
                mx0 = fmaxf(mx0, fmaxf(sacc[nf][0], sacc[nf][1]));
                mx1 = fmaxf(mx1, fmaxf(sacc[nf][2], sacc[nf][3]));
            }
            mx0 = fmaxf(mx0, __shfl_xor_sync(0xffffffffu, mx0, 1));
            mx0 = fmaxf(mx0, __shfl_xor_sync(0xffffffffu, mx0, 2));
            mx1 = fmaxf(mx1, __shfl_xor_sync(0xffffffffu, mx1, 1));
            mx1 = fmaxf(mx1, __shfl_xor_sync(0xffffffffu, mx1, 2));

            const float nm0 = fmaxf(m0r, mx0);
            const float nm1 = fmaxf(m1r, mx1);
            const float cr0 = __expf(m0r - nm0);
            const float cr1 = __expf(m1r - nm1);
            float sum0 = 0.f, sum1 = 0.f;
#pragma unroll
            for (int nf = 0; nf < 8; nf++) {
                sacc[nf][0] = __expf(sacc[nf][0] - nm0);
                sacc[nf][1] = __expf(sacc[nf][1] - nm0);
                sacc[nf][2] = __expf(sacc[nf][2] - nm1);
                sacc[nf][3] = __expf(sacc[nf][3] - nm1);
                sum0 += sacc[nf][0] + sacc[nf][1];
                sum1 += sacc[nf][2] + sacc[nf][3];
            }
            sum0 += __shfl_xor_sync(0xffffffffu, sum0, 1);
            sum0 += __shfl_xor_sync(0xffffffffu, sum0, 2);
            sum1 += __shfl_xor_sync(0xffffffffu, sum1, 1);
            sum1 += __shfl_xor_sync(0xffffffffu, sum1, 2);

            l0r = l0r * cr0 + sum0;
            l1r = l1r * cr1 + sum1;
            m0r = nm0; m1r = nm1;
#pragma unroll
            for (int nf = 0; nf < 8; nf++) {
                o[nf][0] *= cr0; o[nf][1] *= cr0;
                o[nf][2] *= cr1; o[nf][3] *= cr1;
            }

            const int qbase = lane & ~3;
            const int srcA  = qbase | (lc >> 1);
            const int srcB  = srcA + 2;
#pragma unroll
            for (int kc = 0; kc < 8; kc++) {
                const float p0a = __shfl_sync(0xffffffffu, sacc[kc][0], srcA);
                const float p1a = __shfl_sync(0xffffffffu, sacc[kc][1], srcA);
                const float p2a = __shfl_sync(0xffffffffu, sacc[kc][2], srcA);
                const float p3a = __shfl_sync(0xffffffffu, sacc[kc][3], srcA);
                const float p0b = __shfl_sync(0xffffffffu, sacc[kc][0], srcB);
                const float p1b = __shfl_sync(0xffffffffu, sacc[kc][1], srcB);
                const float p2b = __shfl_sync(0xffffffffu, sacc[kc][2], srcB);
                const float p3b = __shfl_sync(0xffffffffu, sacc[kc][3], srcB);
                uint32_t af[4];
                const bool odd = (lc & 1);
                af[0] = __float_as_uint(odd ? p1a : p0a);
                af[1] = __float_as_uint(odd ? p3a : p2a);
                af[2] = __float_as_uint(odd ? p1b : p0b);
                af[3] = __float_as_uint(odd ? p3b : p2b);
#pragma unroll
                for (int nf = 0; nf < 8; nf++) {
                    uint32_t bfr[2];
                    bfr[0] = __float_as_uint(Vs[(8 * kc + lc)     * VS_STRIDE + 8 * nf + lr]);
                    bfr[1] = __float_as_uint(Vs[(8 * kc + lc + 4) * VS_STRIDE + 8 * nf + lr]);
                    mma_tf32(o[nf], af, bfr);
                }
            }
        }
        p ^= 1;
    }

    const float inv0 = 1.0f / l0r;
    const float inv1 = 1.0f / l1r;
    float* O0 = O + (size_t)(b * L + wrow + lr) * D_MODEL + h * DK_;
    float* O1 = O + (size_t)(b * L + wrow + lr + 8) * D_MODEL + h * DK_;
#pragma unroll
    for (int nf = 0; nf < 8; nf++) {
        const int c = 8 * nf + 2 * lc;
        *(float2*)(O0 + c) = make_float2(o[nf][0] * inv0, o[nf][1] * inv0);
        *(float2*)(O1 + c) = make_float2(o[nf][2] * inv1, o[nf][3] * inv1);
    }
}

// ---------------------------------------------------------------------------
// Fused residual add + LayerNorm over last dim (1024). 1 block / row.
// ---------------------------------------------------------------------------
__global__ __launch_bounds__(128)
void add_layernorm(const float* __restrict__ A, const float* __restrict__ Bb,
                   const float* __restrict__ g, const float* __restrict__ be,
                   float* __restrict__ out)
{
    const int row = blockIdx.x;
    const int t = threadIdx.x;
    const float* a = A  + (size_t)row * D_MODEL;
    const float* b = Bb + (size_t)row * D_MODEL;

    float v[8];
    float s = 0.f, sq = 0.f;
#pragma unroll
    for (int i = 0; i < 8; i++) {
        const int c = t + i * 128;
        v[i] = a[c] + b[c];
        s += v[i];
        sq = fmaf(v[i], v[i], sq);
    }
#pragma unroll
    for (int o = 16; o > 0; o >>= 1) {
        s  += __shfl_down_sync(0xffffffffu, s,  o);
        sq += __shfl_down_sync(0xffffffffu, sq, o);
    }
    __shared__ float rs[4], rq[4];
    __shared__ float mean_s, rstd_s;
    const int w = t >> 5, ln = t & 31;
    if (ln == 0) { rs[w] = s; rq[w] = sq; }
    __syncthreads();
    if (t == 0) {
        const float S  = rs[0] + rs[1] + rs[2] + rs[3];
        const float Q2 = rq[0] + rq[1] + rq[2] + rq[3];
        const float mean = S * (1.0f / 1024.0f);
        const float var  = Q2 * (1.0f / 1024.0f) - mean * mean;
        mean_s = mean;
        rstd_s = rsqrtf(var + 1e-5f);
    }
    __syncthreads();
    const float mean = mean_s, rstd = rstd_s;
    float* op = out + (size_t)row * D_MODEL;
#pragma unroll
    for (int i = 0; i < 8; i++) {
        const int c = t + i * 128;
        op[c] = (v[i] - mean) * rstd * g[c] + be[c];
    }
}

// ---------------------------------------------------------------------------
// Host launcher
// ---------------------------------------------------------------------------
static float* devptr(const void* sym) {
    void* p = nullptr;
    cudaGetSymbolAddress(&p, sym);
    return (float*)p;
}

extern "C" void kernel_launch(void* const* d_in, const int* in_sizes, int n_in,
                              void* d_out, int out_size)
{
    const float* x   = (const float*)d_in[0];
    const float* enc = (const float*)d_in[1];
    const float* swq = (const float*)d_in[4];
    const float* sbq = (const float*)d_in[5];
    const float* swk = (const float*)d_in[6];
    const float* sbk = (const float*)d_in[7];
    const float* swv = (const float*)d_in[8];
    const float* sbv = (const float*)d_in[9];
    const float* swo = (const float*)d_in[10];
    const float* sbo = (const float*)d_in[11];
    const float* cwq = (const float*)d_in[12];
    const float* cbq = (const float*)d_in[13];
    const float* cwk = (const float*)d_in[14];
    const float* cbk = (const float*)d_in[15];
    const float* cwv = (const float*)d_in[16];
    const float* cbv = (const float*)d_in[17];
    const float* cwo = (const float*)d_in[18];
    const float* cbo = (const float*)d_in[19];
    const float* fw1 = (const float*)d_in[20];
    const float* fb1 = (const float*)d_in[21];
    const float* fw2 = (const float*)d_in[22];
    const float* fb2 = (const float*)d_in[23];
    const float* n1g = (const float*)d_in[24];
    const float* n1b = (const float*)d_in[25];
    const float* n2g = (const float*)d_in[26];
    const float* n2b = (const float*)d_in[27];
    const float* n3g = (const float*)d_in[28];
    const float* n3b = (const float*)d_in[29];
    float* out = (float*)d_out;

    float* q    = devptr(g_q);
    float* k    = devptr(g_k);
    float* v    = devptr(g_v);
    float* ctx  = devptr(g_ctx);
    float* proj = devptr(g_proj);
    float* x1   = devptr(g_x1);
    float* x2   = devptr(g_x2);
    float* ff   = devptr(g_ff);

    static bool attr_done = false;
    if (!attr_done) {
        cudaFuncSetAttribute(flash_attn_tc<true>,  cudaFuncAttributeMaxDynamicSharedMemorySize, ATTN_SMEM);
        cudaFuncSetAttribute(flash_attn_tc<false>, cudaFuncAttributeMaxDynamicSharedMemorySize, ATTN_SMEM);
        attr_done = true;
    }

    const int M = MROWS, Dm = D_MODEL, Dff = DFF_;
    dim3 blk(256);
    dim3 gP1(Dm  / GBN, M / GBM, 1);   // single GEMM
    dim3 gP2(Dm  / GBN, M / GBM, 2);   // 2-batch
    dim3 gP3(Dm  / GBN, M / GBM, 3);   // 3-batch
    dim3 gF1(Dff / GBN, M / GBM, 1);
    dim3 gA (SEQL / 128, 32);          // (16, B*H)

    auto mk1 = [](const float* B0, const float* b0, float* C0) {
        GemmBatch g; g.B[0] = B0; g.bias[0] = b0; g.C[0] = C0;
        g.B[1] = g.B[2] = B0; g.bias[1] = g.bias[2] = b0; g.C[1] = g.C[2] = C0;
        return g;
    };

    // ---- self attention: QKV fused into one launch ----
    {
        GemmBatch g;
        g.B[0] = swq; g.bias[0] = sbq; g.C[0] = q;
        g.B[1] = swk; g.bias[1] = sbk; g.C[1] = k;
        g.B[2] = swv; g.bias[2] = sbv; g.C[2] = v;
        gemm_tf32<0><<<gP3, blk>>>(x, g, M, Dm, Dm);
    }
    flash_attn_tc<true><<<gA, 256, ATTN_SMEM>>>(q, k, v, ctx, SEQL);
    gemm_tf32<0><<<gP1, blk>>>(ctx, mk1(swo, sbo, proj), M, Dm, Dm);
    add_layernorm<<<M, 128>>>(x, proj, n1g, n1b, x1);

    // ---- cross attention: Q then fused enc-K/V ----
    gemm_tf32<0><<<gP1, blk>>>(x1, mk1(cwq, cbq, q), M, Dm, Dm);
    {
        GemmBatch g;
        g.B[0] = cwk; g.bias[0] = cbk; g.C[0] = k;
        g.B[1] = cwv; g.bias[1] = cbv; g.C[1] = v;
        g.B[2] = cwk; g.bias[2] = cbk; g.C[2] = k;
        gemm_tf32<0><<<gP2, blk>>>(enc, g, M, Dm, Dm);
    }
    flash_attn_tc<false><<<gA, 256, ATTN_SMEM>>>(q, k, v, ctx, SEQL);
    gemm_tf32<0><<<gP1, blk>>>(ctx, mk1(cwo, cbo, proj), M, Dm, Dm);
    add_layernorm<<<M, 128>>>(x1, proj, n2g, n2b, x2);

    // ---- feed-forward ----
    gemm_tf32<1><<<gF1, blk>>>(x2, mk1(fw1, fb1, ff), M, Dff, Dm);
    gemm_tf32<0><<<gP1, blk>>>(ff, mk1(fw2, fb2, proj), M, Dm, Dff);
    add_layernorm<<<M, 128>>>(x2, proj, n3g, n3b, out);
}

// round 15
// speedup vs baseline: 1.9502x; 1.3095x over previous
#include <cuda_runtime.h>
#include <cuda_fp16.h>
#include <math.h>
#include <stdint.h>

// Problem constants
#define D_MODEL 1024
#define NH      16
#define DK_     64
#define MROWS   4096      // B*L = 2*2048
#define DFF_    4096
#define SEQL    2048

// ---------------------------------------------------------------------------
// Scratch (static device globals; no allocations allowed)
// ---------------------------------------------------------------------------
__device__ float  g_q   [MROWS * D_MODEL];
__device__ float  g_k   [MROWS * D_MODEL];
__device__ float  g_v   [MROWS * D_MODEL];
__device__ float  g_proj[MROWS * D_MODEL];
__device__ float  g_x1  [MROWS * D_MODEL];
__device__ float  g_x2  [MROWS * D_MODEL];
// fp16 operands for GEMMs
__device__ __half g_wh  [16 * 1024 * 1024];   // 8x1M projT + 4M fw1T + 4M fw2T
__device__ __half g_xh  [MROWS * D_MODEL];
__device__ __half g_eh  [MROWS * D_MODEL];
__device__ __half g_x1h [MROWS * D_MODEL];
__device__ __half g_x2h [MROWS * D_MODEL];
__device__ __half g_ctxh[MROWS * D_MODEL];
__device__ __half g_ffh [MROWS * DFF_];

__device__ __forceinline__ float gelu_exact(float x) {
    return 0.5f * x * (1.0f + erff(x * 0.70710678118654752f));
}

__device__ __forceinline__ uint32_t to_tf32_bits(float x) {
    uint32_t u;
    asm volatile("cvt.rna.tf32.f32 %0, %1;" : "=r"(u) : "f"(x));
    return u;
}
__device__ __forceinline__ float to_tf32(float x) {
    return __uint_as_float(to_tf32_bits(x));
}

__device__ __forceinline__ void mma_tf32(float* c, const uint32_t* a, const uint32_t* b) {
    asm volatile(
        "mma.sync.aligned.m16n8k8.row.col.f32.tf32.tf32.f32 "
        "{%0,%1,%2,%3}, {%4,%5,%6,%7}, {%8,%9}, {%0,%1,%2,%3};\n"
        : "+f"(c[0]), "+f"(c[1]), "+f"(c[2]), "+f"(c[3])
        : "r"(a[0]), "r"(a[1]), "r"(a[2]), "r"(a[3]), "r"(b[0]), "r"(b[1]));
}

__device__ __forceinline__ void mma_f16(float* c, const uint32_t* a, const uint32_t* b) {
    asm volatile(
        "mma.sync.aligned.m16n8k16.row.col.f32.f16.f16.f32 "
        "{%0,%1,%2,%3}, {%4,%5,%6,%7}, {%8,%9}, {%0,%1,%2,%3};\n"
        : "+f"(c[0]), "+f"(c[1]), "+f"(c[2]), "+f"(c[3])
        : "r"(a[0]), "r"(a[1]), "r"(a[2]), "r"(a[3]), "r"(b[0]), "r"(b[1]));
}

// cp.async helpers
__device__ __forceinline__ void cp_async16(void* smem, const void* gmem) {
    uint32_t s = (uint32_t)__cvta_generic_to_shared(smem);
    asm volatile("cp.async.cg.shared.global [%0], [%1], 16;\n" :: "r"(s), "l"(gmem));
}
__device__ __forceinline__ void cp_commit() {
    asm volatile("cp.async.commit_group;\n" ::: "memory");
}
template<int N>
__device__ __forceinline__ void cp_wait() {
    asm volatile("cp.async.wait_group %0;\n" :: "n"(N) : "memory");
}

// ---------------------------------------------------------------------------
// Pre-pass: transpose weights [K,N] -> [N,K] with fp16 RNE; convert acts.
// ---------------------------------------------------------------------------
__global__ __launch_bounds__(256)
void transpose_h(const float* __restrict__ W, __half* __restrict__ WT, int K, int N)
{
    __shared__ float tile[32][33];
    const int tx = threadIdx.x & 31;
    const int ty = threadIdx.x >> 5;       // 0..7
    const int n0 = blockIdx.x * 32;
    const int k0 = blockIdx.y * 32;
#pragma unroll
    for (int j = 0; j < 4; j++)
        tile[ty + 8 * j][tx] = W[(size_t)(k0 + ty + 8 * j) * N + n0 + tx];
    __syncthreads();
#pragma unroll
    for (int j = 0; j < 4; j++)
        WT[(size_t)(n0 + ty + 8 * j) * K + k0 + tx] = __float2half_rn(tile[tx][ty + 8 * j]);
}

__global__ __launch_bounds__(256)
void convert_h(const float* __restrict__ in, __half* __restrict__ out, int n4)
{
    const int stride = gridDim.x * 256;
    for (int idx = blockIdx.x * 256 + threadIdx.x; idx < n4; idx += stride) {
        float4 v = ((const float4*)in)[idx];
        ((__half2*)out)[2 * idx]     = __floats2half2_rn(v.x, v.y);
        ((__half2*)out)[2 * idx + 1] = __floats2half2_rn(v.z, v.w);
    }
}

// ---------------------------------------------------------------------------
// FP16 tensor-core GEMM (m16n8k16): C[M,N] = A[M,K] @ BT[N,K]^T + bias.
// A: [M,K] fp16. BT: [N,K] fp16 (transposed weights). Bias fp32.
// CTA tile 128x128, 8 warps (2x4), warp tile 64x32, KB=16 per stage,
// 3-stage cp.async (R4-proven schedule). Smem row stride 24 halfs
// (bank = 12*lr+lc distinct -> conflict-free fragment LDS).
// OUTH=0: write fp32 C. OUTH=1: write fp16 C (half2), for GEMM consumers.
// Batched over blockIdx.z (shared A, up to 3 B/bias/C).
// ---------------------------------------------------------------------------
#define GBM 128
#define GBN 128
#define HBK 16
#define HSTR 24
#define STAGES 3

struct GemmBatch {
    const __half* B[3];
    const float*  bias[3];
    void*         C[3];
};

template<int ACT, int OUTH>
__global__ __launch_bounds__(256, 2)
void gemm_f16(const __half* __restrict__ A, GemmBatch gb,
              int M, int N, int K)
{
    __shared__ __half As[STAGES][GBM][HSTR];   // 18432 B
    __shared__ __half Bs[STAGES][GBN][HSTR];   // 18432 B

    const __half* __restrict__ Bw   = gb.B[blockIdx.z];
    const float*  __restrict__ bias = gb.bias[blockIdx.z];
    void*                      Cout = gb.C[blockIdx.z];

    const int t    = threadIdx.x;
    const int wid  = t >> 5;
    const int lane = t & 31;
    const int wm   = wid >> 2;        // 0..1
    const int wn   = wid & 3;         // 0..3
    const int lr   = lane >> 2;       // 0..7
    const int lc   = lane & 3;        // 0..3

    const int m0 = blockIdx.y * GBM;
    const int n0 = blockIdx.x * GBN;

    // cp.async: 128 rows x 32B per operand tile = 256 chunks, 1/thread
    const int row  = t >> 1;          // 0..127
    const int co   = (t & 1) * 8;     // half offset 0 or 8

    const __half* Ag = A  + (size_t)(m0 + row) * K + co;
    const __half* Bg = Bw + (size_t)(n0 + row) * K + co;

    float acc[4][4][4];
#pragma unroll
    for (int i = 0; i < 4; i++)
#pragma unroll
        for (int j = 0; j < 4; j++)
#pragma unroll
            for (int r = 0; r < 4; r++) acc[i][j][r] = 0.0f;

    const int kTiles = K / HBK;

#pragma unroll
    for (int s = 0; s < 2; s++) {
        cp_async16(&As[s][row][co], Ag + (size_t)s * HBK);
        cp_async16(&Bs[s][row][co], Bg + (size_t)s * HBK);
        cp_commit();
    }

    int p = 0;
    for (int kt = 0; kt < kTiles; kt++) {
        cp_wait<1>();
        __syncthreads();

        // ---- compute stage p (K=16): 16 mma per warp ----
        uint32_t afr[4][4];
        uint32_t bfr[4][2];
#pragma unroll
        for (int mf = 0; mf < 4; mf++) {
            const int m = wm * 64 + mf * 16;
            afr[mf][0] = *(const uint32_t*)&As[p][m + lr    ][2 * lc];
            afr[mf][1] = *(const uint32_t*)&As[p][m + lr + 8][2 * lc];
            afr[mf][2] = *(const uint32_t*)&As[p][m + lr    ][2 * lc + 8];
            afr[mf][3] = *(const uint32_t*)&As[p][m + lr + 8][2 * lc + 8];
        }
#pragma unroll
        for (int nf = 0; nf < 4; nf++) {
            const int n = wn * 32 + nf * 8;
            bfr[nf][0] = *(const uint32_t*)&Bs[p][n + lr][2 * lc];
            bfr[nf][1] = *(const uint32_t*)&Bs[p][n + lr][2 * lc + 8];
        }
#pragma unroll
        for (int mf = 0; mf < 4; mf++)
#pragma unroll
            for (int nf = 0; nf < 4; nf++)
                mma_f16(acc[mf][nf], afr[mf], bfr[nf]);

        // ---- issue stage kt+2 ----
        if (kt + 2 < kTiles) {
            const int s = (p + 2) % STAGES;
            const size_t ko = (size_t)(kt + 2) * HBK;
            cp_async16(&As[s][row][co], Ag + ko);
            cp_async16(&Bs[s][row][co], Bg + ko);
        }
        cp_commit();

        p = (p + 1) % STAGES;
        __syncthreads();
    }

    // Epilogue
#pragma unroll
    for (int mf = 0; mf < 4; mf++) {
        const int r0 = m0 + wm * 64 + mf * 16 + lr;
#pragma unroll
        for (int nf = 0; nf < 4; nf++) {
            const int c0 = n0 + wn * 32 + nf * 8 + 2 * lc;
            const float b0 = bias[c0], b1 = bias[c0 + 1];
            float v0 = acc[mf][nf][0] + b0;
            float v1 = acc[mf][nf][1] + b1;
            float v2 = acc[mf][nf][2] + b0;
            float v3 = acc[mf][nf][3] + b1;
            if (ACT == 1) {
                v0 = gelu_exact(v0); v1 = gelu_exact(v1);
                v2 = gelu_exact(v2); v3 = gelu_exact(v3);
            }
            if (OUTH) {
                __half* C = (__half*)Cout;
                *(__half2*)(C + (size_t)r0 * N + c0)       = __floats2half2_rn(v0, v1);
                *(__half2*)(C + (size_t)(r0 + 8) * N + c0) = __floats2half2_rn(v2, v3);
            } else {
                float* C = (float*)Cout;
                *(float2*)(C + (size_t)r0 * N + c0)       = make_float2(v0, v1);
                *(float2*)(C + (size_t)(r0 + 8) * N + c0) = make_float2(v2, v3);
            }
        }
    }
}

// ---------------------------------------------------------------------------
// Tensor-core flash attention (TF32 mma), DK=64 — R12 EXACT structure
// (cp.async double-buffered K/V). Output written as fp16 (sole consumer:
// the O-projection GEMM).
// ---------------------------------------------------------------------------
#define KS_STRIDE 68
#define VS_STRIDE 72
#define KS_ELEMS (64 * KS_STRIDE)
#define VS_ELEMS (64 * VS_STRIDE)
#define ATTN_SMEM ((2 * KS_ELEMS + 2 * VS_ELEMS) * 4)   // 71680 B

template<bool CAUSAL>
__global__ __launch_bounds__(256)
void flash_attn_tc(const float* __restrict__ Q, const float* __restrict__ K,
                   const float* __restrict__ V, __half* __restrict__ O, int L)
{
    extern __shared__ float asmem[];
    float* KsB = asmem;
    float* VsB = asmem + 2 * KS_ELEMS;

    const int t    = threadIdx.x;
    const int lane = t & 31;
    const int w    = t >> 5;
    const int lr   = lane >> 2;
    const int lc   = lane & 3;

    const int qt = blockIdx.x;
    const int bh = blockIdx.y;
    const int b  = bh >> 4;
    const int h  = bh & 15;
    const int q0 = qt * 128;
    const int wrow = q0 + w * 16;

    const float* Qb = Q + (size_t)(b * L) * D_MODEL + h * DK_;
    const float* Kb = K + (size_t)(b * L) * D_MODEL + h * DK_;
    const float* Vb = V + (size_t)(b * L) * D_MODEL + h * DK_;

    int ldrow[4], ldc4[4];
#pragma unroll
    for (int i = 0; i < 4; i++) {
        const int idx = i * 256 + t;
        ldrow[i] = idx >> 4;
        ldc4[i]  = (idx & 15) * 4;
    }

    uint32_t qf[8][4];
    {
        const float* qr0 = Qb + (size_t)(wrow + lr) * D_MODEL;
        const float* qr1 = Qb + (size_t)(wrow + lr + 8) * D_MODEL;
#pragma unroll
        for (int kc = 0; kc < 8; kc++) {
            qf[kc][0] = to_tf32_bits(0.125f * qr0[8 * kc + lc]);
            qf[kc][1] = to_tf32_bits(0.125f * qr1[8 * kc + lc]);
            qf[kc][2] = to_tf32_bits(0.125f * qr0[8 * kc + lc + 4]);
            qf[kc][3] = to_tf32_bits(0.125f * qr1[8 * kc + lc + 4]);
        }
    }

    float o[8][4];
#pragma unroll
    for (int nf = 0; nf < 8; nf++)
#pragma unroll
        for (int i = 0; i < 4; i++) o[nf][i] = 0.0f;
    float m0r = -1e30f, m1r = -1e30f;
    float l0r = 0.0f,  l1r = 0.0f;

    const int ntile = CAUSAL ? (2 * qt + 2) : (L >> 6);

#pragma unroll
    for (int i = 0; i < 4; i++) {
        const size_t g = (size_t)ldrow[i] * D_MODEL + ldc4[i];
        cp_async16(&KsB[0 * KS_ELEMS + ldrow[i] * KS_STRIDE + ldc4[i]], Kb + g);
        cp_async16(&VsB[0 * VS_ELEMS + ldrow[i] * VS_STRIDE + ldc4[i]], Vb + g);
    }
    cp_commit();

    int p = 0;
    for (int kt = 0; kt < ntile; kt++) {
        cp_wait<0>();
        __syncthreads();

        if (kt + 1 < ntile) {
            const int k0n = (kt + 1) * 64;
            const int q2 = p ^ 1;
#pragma unroll
            for (int i = 0; i < 4; i++) {
                const size_t g = (size_t)(k0n + ldrow[i]) * D_MODEL + ldc4[i];
                cp_async16(&KsB[q2 * KS_ELEMS + ldrow[i] * KS_STRIDE + ldc4[i]], Kb + g);
                cp_async16(&VsB[q2 * VS_ELEMS + ldrow[i] * VS_STRIDE + ldc4[i]], Vb + g);
            }
        }
        cp_commit();

        const int k0 = kt * 64;
        const bool active = (!CAUSAL) || (k0 <= wrow + 15);
        if (active) {
            const float* Ks = KsB + p * KS_ELEMS;
            const float* Vs = VsB + p * VS_ELEMS;

            float sacc[8][4];
#pragma unroll
            for (int nf = 0; nf < 8; nf++) {
                sacc[nf][0] = sacc[nf][1] = sacc[nf][2] = sacc[nf][3] = 0.0f;
#pragma unroll
                for (int kc = 0; kc < 8; kc++) {
                    uint32_t bfr[2];
                    bfr[0] = __float_as_uint(Ks[(8 * nf + lr) * KS_STRIDE + 8 * kc + lc]);
                    bfr[1] = __float_as_uint(Ks[(8 * nf + lr) * KS_STRIDE + 8 * kc + lc + 4]);
                    mma_tf32(sacc[nf], qf[kc], bfr);
                }
            }

            if (CAUSAL && (k0 + 63 > wrow)) {
                const int r0 = wrow + lr, r1 = wrow + lr + 8;
#pragma unroll
                for (int nf = 0; nf < 8; nf++) {
                    const int key = k0 + 8 * nf + 2 * lc;
                    if (key     > r0) sacc[nf][0] = -1e30f;
                    if (key + 1 > r0) sacc[nf][1] = -1e30f;
                    if (key     > r1) sacc[nf][2] = -1e30f;
                    if (key + 1 > r1) sacc[nf][3] = -1e30f;
                }
            }

            float mx0 = -1e30f, mx1 = -1e30f;
#pragma unroll
            for (int nf = 0; nf < 8; nf++) {
                mx0 = fmaxf(mx0, fmaxf(sacc[nf][0], sacc[nf][1]));
                mx1 = fmaxf(mx1, fmaxf(sacc[nf][2], sacc[nf][3]));
            }
            mx0 = fmaxf(mx0, __shfl_xor_sync(0xffffffffu, mx0, 1));
            mx0 = fmaxf(mx0, __shfl_xor_sync(0xffffffffu, mx0, 2));
            mx1 = fmaxf(mx1, __shfl_xor_sync(0xffffffffu, mx1, 1));
            mx1 = fmaxf(mx1, __shfl_xor_sync(0xffffffffu, mx1, 2));

            const float nm0 = fmaxf(m0r, mx0);
            const float nm1 = fmaxf(m1r, mx1);
            const float cr0 = __expf(m0r - nm0);
            const float cr1 = __expf(m1r - nm1);
            float sum0 = 0.f, sum1 = 0.f;
#pragma unroll
            for (int nf = 0; nf < 8; nf++) {
                sacc[nf][0] = __expf(sacc[nf][0] - nm0);
                sacc[nf][1] = __expf(sacc[nf][1] - nm0);
                sacc[nf][2] = __expf(sacc[nf][2] - nm1);
                sacc[nf][3] = __expf(sacc[nf][3] - nm1);
                sum0 += sacc[nf][0] + sacc[nf][1];
                sum1 += sacc[nf][2] + sacc[nf][3];
            }
            sum0 += __shfl_xor_sync(0xffffffffu, sum0, 1);
            sum0 += __shfl_xor_sync(0xffffffffu, sum0, 2);
            sum1 += __shfl_xor_sync(0xffffffffu, sum1, 1);
            sum1 += __shfl_xor_sync(0xffffffffu, sum1, 2);

            l0r = l0r * cr0 + sum0;
            l1r = l1r * cr1 + sum1;
            m0r = nm0; m1r = nm1;
#pragma unroll
            for (int nf = 0; nf < 8; nf++) {
                o[nf][0] *= cr0; o[nf][1] *= cr0;
                o[nf][2] *= cr1; o[nf][3] *= cr1;
            }

            const int qbase = lane & ~3;
            const int srcA  = qbase | (lc >> 1);
            const int srcB  = srcA + 2;
#pragma unroll
            for (int kc = 0; kc < 8; kc++) {
                const float p0a = __shfl_sync(0xffffffffu, sacc[kc][0], srcA);
                const float p1a = __shfl_sync(0xffffffffu, sacc[kc][1], srcA);
                const float p2a = __shfl_sync(0xffffffffu, sacc[kc][2], srcA);
                const float p3a = __shfl_sync(0xffffffffu, sacc[kc][3], srcA);
                const float p0b = __shfl_sync(0xffffffffu, sacc[kc][0], srcB);
                const float p1b = __shfl_sync(0xffffffffu, sacc[kc][1], srcB);
                const float p2b = __shfl_sync(0xffffffffu, sacc[kc][2], srcB);
                const float p3b = __shfl_sync(0xffffffffu, sacc[kc][3], srcB);
                uint32_t af[4];
                const bool odd = (lc & 1);
                af[0] = __float_as_uint(odd ? p1a : p0a);
                af[1] = __float_as_uint(odd ? p3a : p2a);
                af[2] = __float_as_uint(odd ? p1b : p0b);
                af[3] = __float_as_uint(odd ? p3b : p2b);
#pragma unroll
                for (int nf = 0; nf < 8; nf++) {
                    uint32_t bfr[2];
                    bfr[0] = __float_as_uint(Vs[(8 * kc + lc)     * VS_STRIDE + 8 * nf + lr]);
                    bfr[1] = __float_as_uint(Vs[(8 * kc + lc + 4) * VS_STRIDE + 8 * nf + lr]);
                    mma_tf32(o[nf], af, bfr);
                }
            }
        }
        p ^= 1;
    }

    const float inv0 = 1.0f / l0r;
    const float inv1 = 1.0f / l1r;
    __half* O0 = O + (size_t)(b * L + wrow + lr) * D_MODEL + h * DK_;
    __half* O1 = O + (size_t)(b * L + wrow + lr + 8) * D_MODEL + h * DK_;
#pragma unroll
    for (int nf = 0; nf < 8; nf++) {
        const int c = 8 * nf + 2 * lc;
        *(__half2*)(O0 + c) = __floats2half2_rn(o[nf][0] * inv0, o[nf][1] * inv0);
        *(__half2*)(O1 + c) = __floats2half2_rn(o[nf][2] * inv1, o[nf][3] * inv1);
    }
}

// ---------------------------------------------------------------------------
// Fused residual add + LayerNorm; DUAL also writes an fp16 copy (for GEMMs).
// ---------------------------------------------------------------------------
template<bool DUAL>
__global__ __launch_bounds__(128)
void add_layernorm(const float* __restrict__ A, const float* __restrict__ Bb,
                   const float* __restrict__ g, const float* __restrict__ be,
                   float* __restrict__ out, __half* __restrict__ out_h)
{
    const int row = blockIdx.x;
    const int t = threadIdx.x;
    const float* a = A  + (size_t)row * D_MODEL;
    const float* b = Bb + (size_t)row * D_MODEL;

    float v[8];
    float s = 0.f, sq = 0.f;
#pragma unroll
    for (int i = 0; i < 8; i++) {
        const int c = t + i * 128;
        v[i] = a[c] + b[c];
        s += v[i];
        sq = fmaf(v[i], v[i], sq);
    }
#pragma unroll
    for (int o = 16; o > 0; o >>= 1) {
        s  += __shfl_down_sync(0xffffffffu, s,  o);
        sq += __shfl_down_sync(0xffffffffu, sq, o);
    }
    __shared__ float rs[4], rq[4];
    __shared__ float mean_s, rstd_s;
    const int w = t >> 5, ln = t & 31;
    if (ln == 0) { rs[w] = s; rq[w] = sq; }
    __syncthreads();
    if (t == 0) {
        const float S  = rs[0] + rs[1] + rs[2] + rs[3];
        const float Q2 = rq[0] + rq[1] + rq[2] + rq[3];
        const float mean = S * (1.0f / 1024.0f);
        const float var  = Q2 * (1.0f / 1024.0f) - mean * mean;
        mean_s = mean;
        rstd_s = rsqrtf(var + 1e-5f);
    }
    __syncthreads();
    const float mean = mean_s, rstd = rstd_s;
    float* op = out + (size_t)row * D_MODEL;
    __half* ohp = DUAL ? out_h + (size_t)row * D_MODEL : nullptr;
#pragma unroll
    for (int i = 0; i < 8; i++) {
        const int c = t + i * 128;
        const float y = (v[i] - mean) * rstd * g[c] + be[c];
        op[c] = y;
        if (DUAL) ohp[c] = __float2half_rn(y);
    }
}

// ---------------------------------------------------------------------------
// Host launcher
// ---------------------------------------------------------------------------
static void* devptr(const void* sym) {
    void* p = nullptr;
    cudaGetSymbolAddress(&p, sym);
    return p;
}

extern "C" void kernel_launch(void* const* d_in, const int* in_sizes, int n_in,
                              void* d_out, int out_size)
{
    const float* x   = (const float*)d_in[0];
    const float* enc = (const float*)d_in[1];
    const float* swq = (const float*)d_in[4];
    const float* sbq = (const float*)d_in[5];
    const float* swk = (const float*)d_in[6];
    const float* sbk = (const float*)d_in[7];
    const float* swv = (const float*)d_in[8];
    const float* sbv = (const float*)d_in[9];
    const float* swo = (const float*)d_in[10];
    const float* sbo = (const float*)d_in[11];
    const float* cwq = (const float*)d_in[12];
    const float* cbq = (const float*)d_in[13];
    const float* cwk = (const float*)d_in[14];
    const float* cbk = (const float*)d_in[15];
    const float* cwv = (const float*)d_in[16];
    const float* cbv = (const float*)d_in[17];
    const float* cwo = (const float*)d_in[18];
    const float* cbo = (const float*)d_in[19];
    const float* fw1 = (const float*)d_in[20];
    const float* fb1 = (const float*)d_in[21];
    const float* fw2 = (const float*)d_in[22];
    const float* fb2 = (const float*)d_in[23];
    const float* n1g = (const float*)d_in[24];
    const float* n1b = (const float*)d_in[25];
    const float* n2g = (const float*)d_in[26];
    const float* n2b = (const float*)d_in[27];
    const float* n3g = (const float*)d_in[28];
    const float* n3b = (const float*)d_in[29];
    float* out = (float*)d_out;

    float*  q    = (float*)devptr(g_q);
    float*  k    = (float*)devptr(g_k);
    float*  v    = (float*)devptr(g_v);
    float*  proj = (float*)devptr(g_proj);
    float*  x1   = (float*)devptr(g_x1);
    float*  x2   = (float*)devptr(g_x2);
    __half* wh   = (__half*)devptr(g_wh);
    __half* xh   = (__half*)devptr(g_xh);
    __half* eh   = (__half*)devptr(g_eh);
    __half* x1h  = (__half*)devptr(g_x1h);
    __half* x2h  = (__half*)devptr(g_x2h);
    __half* ctxh = (__half*)devptr(g_ctxh);
    __half* ffh  = (__half*)devptr(g_ffh);

    static bool attr_done = false;
    if (!attr_done) {
        cudaFuncSetAttribute(flash_attn_tc<true>,  cudaFuncAttributeMaxDynamicSharedMemorySize, ATTN_SMEM);
        cudaFuncSetAttribute(flash_attn_tc<false>, cudaFuncAttributeMaxDynamicSharedMemorySize, ATTN_SMEM);
        attr_done = true;
    }

    const int M = MROWS, Dm = D_MODEL, Dff = DFF_;
    const int W1 = Dm * Dm;
    dim3 blk(256);
    dim3 gP1(Dm  / GBN, M / GBM, 1);
    dim3 gP2(Dm  / GBN, M / GBM, 2);
    dim3 gP3(Dm  / GBN, M / GBM, 3);
    dim3 gF1(Dff / GBN, M / GBM, 1);
    dim3 gA (SEQL / 128, 32);
    dim3 gT (32, 32);                 // 1024x1024 transpose
    dim3 gT1(128, 32);                // fw1 [1024,4096] -> [4096,1024]
    dim3 gT2(32, 128);                // fw2 [4096,1024] -> [1024,4096]

    // ---- pre-pass: weights transpose+fp16; activations fp16 ----
    transpose_h<<<gT, blk>>>(swq, wh + 0 * W1, Dm, Dm);
    transpose_h<<<gT, blk>>>(swk, wh + 1 * W1, Dm, Dm);
    transpose_h<<<gT, blk>>>(swv, wh + 2 * W1, Dm, Dm);
    transpose_h<<<gT, blk>>>(swo, wh + 3 * W1, Dm, Dm);
    transpose_h<<<gT, blk>>>(cwq, wh + 4 * W1, Dm, Dm);
    transpose_h<<<gT, blk>>>(cwk, wh + 5 * W1, Dm, Dm);
    transpose_h<<<gT, blk>>>(cwv, wh + 6 * W1, Dm, Dm);
    transpose_h<<<gT, blk>>>(cwo, wh + 7 * W1, Dm, Dm);
    transpose_h<<<gT1, blk>>>(fw1, wh + 8 * W1,  Dm, Dff);
    transpose_h<<<gT2, blk>>>(fw2, wh + 12 * W1, Dff, Dm);
    convert_h<<<1024, 256>>>(x,   xh, M * Dm / 4);
    convert_h<<<1024, 256>>>(enc, eh, M * Dm / 4);

    auto mk1 = [](const __half* B0, const float* b0, void* C0) {
        GemmBatch g; g.B[0] = B0; g.bias[0] = b0; g.C[0] = C0;
        g.B[1] = g.B[2] = B0; g.bias[1] = g.bias[2] = b0; g.C[1] = g.C[2] = C0;
        return g;
    };

    // ---- self attention: QKV fused ----
    {
        GemmBatch g;
        g.B[0] = wh + 0 * W1; g.bias[0] = sbq; g.C[0] = q;
        g.B[1] = wh + 1 * W1; g.bias[1] = sbk; g.C[1] = k;
        g.B[2] = wh + 2 * W1; g.bias[2] = sbv; g.C[2] = v;
        gemm_f16<0, 0><<<gP3, blk>>>(xh, g, M, Dm, Dm);
    }
    flash_attn_tc<true><<<gA, 256, ATTN_SMEM>>>(q, k, v, ctxh, SEQL);
    gemm_f16<0, 0><<<gP1, blk>>>(ctxh, mk1(wh + 3 * W1, sbo, proj), M, Dm, Dm);
    add_layernorm<true><<<M, 128>>>(x, proj, n1g, n1b, x1, x1h);

    // ---- cross attention ----
    gemm_f16<0, 0><<<gP1, blk>>>(x1h, mk1(wh + 4 * W1, cbq, q), M, Dm, Dm);
    {
        GemmBatch g;
        g.B[0] = wh + 5 * W1; g.bias[0] = cbk; g.C[0] = k;
        g.B[1] = wh + 6 * W1; g.bias[1] = cbv; g.C[1] = v;
        g.B[2] = wh + 5 * W1; g.bias[2] = cbk; g.C[2] = k;
        gemm_f16<0, 0><<<gP2, blk>>>(eh, g, M, Dm, Dm);
    }
    flash_attn_tc<false><<<gA, 256, ATTN_SMEM>>>(q, k, v, ctxh, SEQL);
    gemm_f16<0, 0><<<gP1, blk>>>(ctxh, mk1(wh + 7 * W1, cbo, proj), M, Dm, Dm);
    add_layernorm<true><<<M, 128>>>(x1, proj, n2g, n2b, x2, x2h);

    // ---- feed-forward ----
    gemm_f16<1, 1><<<gF1, blk>>>(x2h, mk1(wh + 8 * W1, fb1, ffh), M, Dff, Dm);
    gemm_f16<0, 0><<<gP1, blk>>>(ffh, mk1(wh + 12 * W1, fb2, proj), M, Dm, Dff);
    add_layernorm<false><<<M, 128>>>(x2, proj, n3g, n3b, out, nullptr);
}